// round 3
// baseline (speedup 1.0000x reference)
#include <cuda_runtime.h>
#include <cuda_fp16.h>
#include <cstdint>

// ===================== problem dims =====================
#define M_DIM 8192      // B*S = 4*2048
#define N_DIM 16384
#define K_DIM 4096

#define BM 256
#define BN 128
#define BK 64                         // halves per K-chunk (128 bytes per row)
#define NCHUNK (K_DIM / BK)           // 64
#define STAGES 4
#define THREADS 256
#define TILES_M (M_DIM / BM)          // 32
#define TILES_N (N_DIM / BN)          // 128
#define GROUP_M 8                     // raster: m-tiles per group (m fastest)

// ===================== scratch (alloc-free) =====================
__device__ __half g_A[(size_t)M_DIM * K_DIM];   // 64 MB fp16 activations
__device__ __half g_B[(size_t)N_DIM * K_DIM];   // 128 MB fp16 weights (exact int8 values)

// ===================== PTX helpers (baseline features only) =====================
__device__ __forceinline__ uint32_t smem_to_u32(const void* p) {
    uint32_t a;
    asm("{ .reg .u64 t; cvta.to.shared.u64 t, %1; cvt.u32.u64 %0, t; }" : "=r"(a) : "l"(p));
    return a;
}
__device__ __forceinline__ void cp_async16(uint32_t dst, const void* src) {
    asm volatile("cp.async.cg.shared.global [%0], [%1], 16;" :: "r"(dst), "l"(src));
}
__device__ __forceinline__ void cp_commit() {
    asm volatile("cp.async.commit_group;" ::: "memory");
}
template <int N>
__device__ __forceinline__ void cp_wait() {
    asm volatile("cp.async.wait_group %0;" :: "n"(N) : "memory");
}
__device__ __forceinline__ void ldsm_x4(uint32_t* r, uint32_t addr) {
    asm volatile("ldmatrix.sync.aligned.m8n8.x4.shared.b16 {%0,%1,%2,%3}, [%4];"
                 : "=r"(r[0]), "=r"(r[1]), "=r"(r[2]), "=r"(r[3]) : "r"(addr));
}
__device__ __forceinline__ void mma16816(float* d, const uint32_t* a, const uint32_t* b) {
    asm volatile(
        "mma.sync.aligned.m16n8k16.row.col.f32.f16.f16.f32 "
        "{%0,%1,%2,%3}, {%4,%5,%6,%7}, {%8,%9}, {%0,%1,%2,%3};"
        : "+f"(d[0]), "+f"(d[1]), "+f"(d[2]), "+f"(d[3])
        : "r"(a[0]), "r"(a[1]), "r"(a[2]), "r"(a[3]), "r"(b[0]), "r"(b[1]));
}

// SW128 swizzle for 128B rows: 16B chunk index ^= (row & 7)
__device__ __forceinline__ uint32_t swz_row_col(int row, int colbytes) {
    return (uint32_t)(row * 128) + (uint32_t)(colbytes ^ ((row & 7) << 4));
}

// ===================== SMEM layout =====================
#define A_STAGE_BYTES (BM * 128)              // 32768
#define B_STAGE_BYTES (BN * 128)              // 16384
#define STAGE_BYTES   (A_STAGE_BYTES + B_STAGE_BYTES)   // 49152
#define SMEM_BODY     (STAGES * STAGE_BYTES)  // 196608
#define SMEM_TOTAL    (SMEM_BODY + 128)       // manual 128B alignment headroom

// ===================== conversion kernels =====================
struct alignas(16) H8 { __half2 a, b, c, d; };

__global__ void cvtA_kernel(const float4* __restrict__ in) {
    size_t i = (size_t)blockIdx.x * blockDim.x + threadIdx.x;
    float4 v0 = in[2 * i];
    float4 v1 = in[2 * i + 1];
    H8 h;
    h.a = __floats2half2_rn(v0.x, v0.y);
    h.b = __floats2half2_rn(v0.z, v0.w);
    h.c = __floats2half2_rn(v1.x, v1.y);
    h.d = __floats2half2_rn(v1.z, v1.w);
    reinterpret_cast<H8*>(g_A)[i] = h;
}

__global__ void cvtW_kernel(const int4* __restrict__ in) {
    size_t i = (size_t)blockIdx.x * blockDim.x + threadIdx.x;
    int4 v0 = in[2 * i];
    int4 v1 = in[2 * i + 1];
    H8 h;
    h.a = __floats2half2_rn((float)v0.x, (float)v0.y);
    h.b = __floats2half2_rn((float)v0.z, (float)v0.w);
    h.c = __floats2half2_rn((float)v1.x, (float)v1.y);
    h.d = __floats2half2_rn((float)v1.z, (float)v1.w);
    reinterpret_cast<H8*>(g_B)[i] = h;
}

// ===================== GEMM kernel (HMMA mma.sync, 4-stage cp.async) =====================
__global__ void __launch_bounds__(THREADS, 1)
gemm_f16_hmma(float* __restrict__ out,
              const float* __restrict__ scale,
              const float* __restrict__ bias) {
    extern __shared__ char smem_raw[];
    char* smem = (char*)(((uintptr_t)smem_raw + 127) & ~(uintptr_t)127);
    const uint32_t sb = smem_to_u32(smem);

    const int tid  = threadIdx.x;
    const int wid  = tid >> 5;
    const int lane = tid & 31;
    const int wm   = wid >> 1;   // 0..3  (m-warp, 64 rows each)
    const int wn   = wid & 1;    // 0..1  (n-warp, 64 cols each)

    // ---- CTA raster swizzle: m fastest within groups of GROUP_M m-tiles ----
    const int bid       = blockIdx.x;
    const int per_group = GROUP_M * TILES_N;           // 1024
    const int g         = bid / per_group;
    const int r_        = bid % per_group;
    const int tile_m    = (g * GROUP_M + (r_ % GROUP_M)) * BM;
    const int tile_n    = (r_ / GROUP_M) * BN;

    const __half* aG = g_A + (size_t)tile_m * K_DIM;
    const __half* bG = g_B + (size_t)tile_n * K_DIM;

    // ldmatrix per-lane row/col-sub mappings (identical to validated round-2 logic)
    const int rowA_in16 = ((lane >> 3) & 1) * 8 + (lane & 7);
    const int ksubA     = ((lane >> 4) & 1) * 16;
    const int rowB_in16 = ((lane >> 4) & 1) * 8 + (lane & 7);
    const int ksubB     = ((lane >> 3) & 1) * 16;

    float acc[4][8][4];
    #pragma unroll
    for (int mt = 0; mt < 4; mt++)
        #pragma unroll
        for (int nt = 0; nt < 8; nt++)
            #pragma unroll
            for (int q = 0; q < 4; q++) acc[mt][nt][q] = 0.0f;

    // ---- producer: A 256 rows x 8 chunks, B 128 rows x 8 chunks (16B each) ----
    auto load_stage = [&](int stage, int kc) {
        const uint32_t sA = sb + stage * STAGE_BYTES;
        const uint32_t sB = sA + A_STAGE_BYTES;
        const int kh = kc * BK;   // half offset
        #pragma unroll
        for (int j = 0; j < 8; j++) {
            int idx = tid + j * 256;
            int r = idx >> 3, c = idx & 7;
            cp_async16(sA + swz_row_col(r, c * 16), aG + (size_t)r * K_DIM + kh + c * 8);
        }
        #pragma unroll
        for (int j = 0; j < 4; j++) {
            int idx = tid + j * 256;
            int r = idx >> 3, c = idx & 7;
            cp_async16(sB + swz_row_col(r, c * 16), bG + (size_t)r * K_DIM + kh + c * 8);
        }
    };

    // ---- prologue ----
    #pragma unroll
    for (int s = 0; s < STAGES - 1; s++) {
        load_stage(s, s);
        cp_commit();
    }
    cp_wait<STAGES - 2>();
    __syncthreads();

    // ---- main loop ----
    for (int kc = 0; kc < NCHUNK; kc++) {
        const int kload = kc + STAGES - 1;
        if (kload < NCHUNK) load_stage(kload % STAGES, kload);
        cp_commit();

        const uint32_t sA = sb + (kc % STAGES) * STAGE_BYTES;
        const uint32_t sB = sA + A_STAGE_BYTES;

        #pragma unroll
        for (int ks = 0; ks < 4; ks++) {          // 4 x k16 per BK=64 chunk
            uint32_t a[4][4];
            #pragma unroll
            for (int mt = 0; mt < 4; mt++) {
                const int row = wm * 64 + mt * 16 + rowA_in16;
                ldsm_x4(a[mt], sA + swz_row_col(row, ks * 32 + ksubA));
            }
            uint32_t b[8][2];
            #pragma unroll
            for (int p = 0; p < 4; p++) {         // each x4 covers two n8-tiles
                const int row = wn * 64 + p * 16 + rowB_in16;
                uint32_t r4[4];
                ldsm_x4(r4, sB + swz_row_col(row, ks * 32 + ksubB));
                b[2 * p][0] = r4[0]; b[2 * p][1] = r4[1];
                b[2 * p + 1][0] = r4[2]; b[2 * p + 1][1] = r4[3];
            }
            #pragma unroll
            for (int mt = 0; mt < 4; mt++)
                #pragma unroll
                for (int nt = 0; nt < 8; nt++)
                    mma16816(acc[mt][nt], a[mt], b[nt]);
        }

        cp_wait<STAGES - 2>();
        __syncthreads();
    }

    // ---- epilogue: scale * acc + bias, direct float2 stores ----
    const int colbase = tile_n + wn * 64 + (lane & 3) * 2;
    float2 sc[8], bi[8];
    #pragma unroll
    for (int nt = 0; nt < 8; nt++) {
        sc[nt] = *reinterpret_cast<const float2*>(scale + colbase + nt * 8);
        bi[nt] = *reinterpret_cast<const float2*>(bias  + colbase + nt * 8);
    }

    #pragma unroll
    for (int mt = 0; mt < 4; mt++) {
        const int grow = tile_m + wm * 64 + mt * 16 + (lane >> 2);
        float* o0 = out + (size_t)grow * N_DIM + colbase;
        float* o1 = o0 + (size_t)8 * N_DIM;
        #pragma unroll
        for (int nt = 0; nt < 8; nt++) {
            float2 v0, v1;
            v0.x = acc[mt][nt][0] * sc[nt].x + bi[nt].x;
            v0.y = acc[mt][nt][1] * sc[nt].y + bi[nt].y;
            v1.x = acc[mt][nt][2] * sc[nt].x + bi[nt].x;
            v1.y = acc[mt][nt][3] * sc[nt].y + bi[nt].y;
            *reinterpret_cast<float2*>(o0 + nt * 8) = v0;
            *reinterpret_cast<float2*>(o1 + nt * 8) = v1;
        }
    }
}

// ===================== launch =====================
extern "C" void kernel_launch(void* const* d_in, const int* in_sizes, int n_in,
                              void* d_out, int out_size) {
    const float* inp  = (const float*)d_in[0];   // (4, 2048, 4096) f32
    const int*   wgt  = (const int*)d_in[1];     // (16384, 4096) int32 (int8-valued)
    const float* wsc  = (const float*)d_in[2];   // (16384,) f32
    const float* bias = (const float*)d_in[3];   // (16384,) f32
    float* out = (float*)d_out;                  // (4, 2048, 16384) f32

    (void)in_sizes; (void)n_in; (void)out_size;

    cvtA_kernel<<<16384, 256>>>(reinterpret_cast<const float4*>(inp));
    cvtW_kernel<<<32768, 256>>>(reinterpret_cast<const int4*>(wgt));

    cudaFuncSetAttribute(gemm_f16_hmma,
                         cudaFuncAttributeMaxDynamicSharedMemorySize, SMEM_TOTAL);
    gemm_f16_hmma<<<TILES_M * TILES_N, THREADS, SMEM_TOTAL>>>(out, wsc, bias);
}

// round 4
// speedup vs baseline: 1.0839x; 1.0839x over previous
#include <cuda_runtime.h>
#include <cuda_fp16.h>
#include <cstdint>

// ===================== problem dims =====================
#define M_DIM 8192      // B*S = 4*2048
#define N_DIM 16384
#define K_DIM 4096

#define BM 128
#define BN 128
#define BK 64                         // halves per K-chunk (128 bytes per row)
#define NCHUNK (K_DIM / BK)           // 64
#define STAGES 3
#define THREADS 256
#define TILES_M (M_DIM / BM)          // 64
#define TILES_N (N_DIM / BN)          // 128
#define GROUP_M 8                     // raster: m-tiles per group (m fastest within group)

// ===================== scratch (alloc-free) =====================
__device__ __half g_A[(size_t)M_DIM * K_DIM];   // 64 MB fp16 activations
__device__ __half g_B[(size_t)N_DIM * K_DIM];   // 128 MB fp16 weights (exact int8 values)

// ===================== PTX helpers (baseline features only) =====================
__device__ __forceinline__ uint32_t smem_to_u32(const void* p) {
    uint32_t a;
    asm("{ .reg .u64 t; cvta.to.shared.u64 t, %1; cvt.u32.u64 %0, t; }" : "=r"(a) : "l"(p));
    return a;
}
__device__ __forceinline__ void cp_async16(uint32_t dst, const void* src) {
    asm volatile("cp.async.cg.shared.global [%0], [%1], 16;" :: "r"(dst), "l"(src));
}
__device__ __forceinline__ void cp_commit() {
    asm volatile("cp.async.commit_group;" ::: "memory");
}
template <int N>
__device__ __forceinline__ void cp_wait() {
    asm volatile("cp.async.wait_group %0;" :: "n"(N) : "memory");
}
__device__ __forceinline__ void ldsm_x4(uint32_t* r, uint32_t addr) {
    asm volatile("ldmatrix.sync.aligned.m8n8.x4.shared.b16 {%0,%1,%2,%3}, [%4];"
                 : "=r"(r[0]), "=r"(r[1]), "=r"(r[2]), "=r"(r[3]) : "r"(addr));
}
__device__ __forceinline__ void mma16816(float* d, const uint32_t* a, const uint32_t* b) {
    asm volatile(
        "mma.sync.aligned.m16n8k16.row.col.f32.f16.f16.f32 "
        "{%0,%1,%2,%3}, {%4,%5,%6,%7}, {%8,%9}, {%0,%1,%2,%3};"
        : "+f"(d[0]), "+f"(d[1]), "+f"(d[2]), "+f"(d[3])
        : "r"(a[0]), "r"(a[1]), "r"(a[2]), "r"(a[3]), "r"(b[0]), "r"(b[1]));
}

// SW128 swizzle for 128B rows: 16B chunk index ^= (row & 7)
__device__ __forceinline__ uint32_t swz_row_col(int row, int colbytes) {
    return (uint32_t)(row * 128) + (uint32_t)(colbytes ^ ((row & 7) << 4));
}

// ===================== SMEM layout =====================
#define A_STAGE_BYTES (BM * 128)              // 16384
#define B_STAGE_BYTES (BN * 128)              // 16384
#define STAGE_BYTES   (A_STAGE_BYTES + B_STAGE_BYTES)   // 32768
#define SMEM_BODY     (STAGES * STAGE_BYTES)  // 98304
#define SMEM_TOTAL    (SMEM_BODY + 128)       // manual 128B alignment headroom

// ===================== conversion kernels =====================
struct alignas(16) H8 { __half2 a, b, c, d; };

__global__ void cvtA_kernel(const float4* __restrict__ in) {
    size_t i = (size_t)blockIdx.x * blockDim.x + threadIdx.x;
    float4 v0 = in[2 * i];
    float4 v1 = in[2 * i + 1];
    H8 h;
    h.a = __floats2half2_rn(v0.x, v0.y);
    h.b = __floats2half2_rn(v0.z, v0.w);
    h.c = __floats2half2_rn(v1.x, v1.y);
    h.d = __floats2half2_rn(v1.z, v1.w);
    reinterpret_cast<H8*>(g_A)[i] = h;
}

__global__ void cvtW_kernel(const int4* __restrict__ in) {
    size_t i = (size_t)blockIdx.x * blockDim.x + threadIdx.x;
    int4 v0 = in[2 * i];
    int4 v1 = in[2 * i + 1];
    H8 h;
    h.a = __floats2half2_rn((float)v0.x, (float)v0.y);
    h.b = __floats2half2_rn((float)v0.z, (float)v0.w);
    h.c = __floats2half2_rn((float)v1.x, (float)v1.y);
    h.d = __floats2half2_rn((float)v1.z, (float)v1.w);
    reinterpret_cast<H8*>(g_B)[i] = h;
}

// ===================== GEMM kernel (HMMA mma.sync, 3-stage cp.async) =====================
__global__ void __launch_bounds__(THREADS, 2)
gemm_f16_hmma(float* __restrict__ out,
              const float* __restrict__ scale,
              const float* __restrict__ bias) {
    extern __shared__ char smem_raw[];
    char* smem = (char*)(((uintptr_t)smem_raw + 127) & ~(uintptr_t)127);
    const uint32_t sb = smem_to_u32(smem);

    const int tid  = threadIdx.x;
    const int wid  = tid >> 5;
    const int lane = tid & 31;
    const int wm   = wid >> 1;   // 0..3  (m-warp)
    const int wn   = wid & 1;    // 0..1  (n-warp)

    // ---- CTA raster swizzle: m fastest within groups of GROUP_M m-tiles ----
    const int bid       = blockIdx.x;
    const int per_group = GROUP_M * TILES_N;           // 1024
    const int g         = bid / per_group;
    const int r_        = bid % per_group;
    const int tile_m    = (g * GROUP_M + (r_ % GROUP_M)) * BM;
    const int tile_n    = (r_ / GROUP_M) * BN;

    const __half* aG = g_A + (size_t)tile_m * K_DIM;
    const __half* bG = g_B + (size_t)tile_n * K_DIM;

    // ldmatrix per-lane row/col-sub mappings (validated round-2 logic)
    const int rowA_in16 = ((lane >> 3) & 1) * 8 + (lane & 7);
    const int ksubA     = ((lane >> 4) & 1) * 16;
    const int rowB_in16 = ((lane >> 4) & 1) * 8 + (lane & 7);
    const int ksubB     = ((lane >> 3) & 1) * 16;

    float acc[2][8][4];
    #pragma unroll
    for (int mt = 0; mt < 2; mt++)
        #pragma unroll
        for (int nt = 0; nt < 8; nt++)
            #pragma unroll
            for (int q = 0; q < 4; q++) acc[mt][nt][q] = 0.0f;

    // ---- producer (all 256 threads): A 128x8 chunks, B 128x8 chunks (16B each) ----
    auto load_stage = [&](int stage, int kc) {
        const uint32_t sA = sb + stage * STAGE_BYTES;
        const uint32_t sB = sA + A_STAGE_BYTES;
        const int kh = kc * BK;   // half offset
        #pragma unroll
        for (int j = 0; j < 4; j++) {
            int idx = tid + j * 256;
            int r = idx >> 3, c = idx & 7;
            cp_async16(sA + swz_row_col(r, c * 16), aG + (size_t)r * K_DIM + kh + c * 8);
        }
        #pragma unroll
        for (int j = 0; j < 4; j++) {
            int idx = tid + j * 256;
            int r = idx >> 3, c = idx & 7;
            cp_async16(sB + swz_row_col(r, c * 16), bG + (size_t)r * K_DIM + kh + c * 8);
        }
    };

    // ---- prologue ----
    #pragma unroll
    for (int s = 0; s < STAGES - 1; s++) {
        load_stage(s, s);
        cp_commit();
    }
    cp_wait<STAGES - 2>();
    __syncthreads();

    // ---- main loop ----
    for (int kc = 0; kc < NCHUNK; kc++) {
        const int kload = kc + STAGES - 1;
        if (kload < NCHUNK) load_stage(kload % STAGES, kload);
        cp_commit();

        const uint32_t sA = sb + (kc % STAGES) * STAGE_BYTES;
        const uint32_t sB = sA + A_STAGE_BYTES;

        #pragma unroll
        for (int ks = 0; ks < 4; ks++) {          // 4 x k16 per BK=64 chunk
            uint32_t a[2][4];
            #pragma unroll
            for (int mt = 0; mt < 2; mt++) {
                const int row = wm * 32 + mt * 16 + rowA_in16;
                ldsm_x4(a[mt], sA + swz_row_col(row, ks * 32 + ksubA));
            }
            uint32_t b[8][2];
            #pragma unroll
            for (int p = 0; p < 4; p++) {         // each x4 covers two n8-tiles
                const int row = wn * 64 + p * 16 + rowB_in16;
                uint32_t r4[4];
                ldsm_x4(r4, sB + swz_row_col(row, ks * 32 + ksubB));
                b[2 * p][0] = r4[0]; b[2 * p][1] = r4[1];
                b[2 * p + 1][0] = r4[2]; b[2 * p + 1][1] = r4[3];
            }
            #pragma unroll
            for (int mt = 0; mt < 2; mt++)
                #pragma unroll
                for (int nt = 0; nt < 8; nt++)
                    mma16816(acc[mt][nt], a[mt], b[nt]);
        }

        cp_wait<STAGES - 2>();
        __syncthreads();
    }

    // ---- epilogue: scale * acc + bias, direct float2 stores ----
    const int colbase = tile_n + wn * 64 + (lane & 3) * 2;
    float2 sc[8], bi[8];
    #pragma unroll
    for (int nt = 0; nt < 8; nt++) {
        sc[nt] = *reinterpret_cast<const float2*>(scale + colbase + nt * 8);
        bi[nt] = *reinterpret_cast<const float2*>(bias  + colbase + nt * 8);
    }

    #pragma unroll
    for (int mt = 0; mt < 2; mt++) {
        const int grow = tile_m + wm * 32 + mt * 16 + (lane >> 2);
        float* o0 = out + (size_t)grow * N_DIM + colbase;
        float* o1 = o0 + (size_t)8 * N_DIM;
        #pragma unroll
        for (int nt = 0; nt < 8; nt++) {
            float2 v0, v1;
            v0.x = acc[mt][nt][0] * sc[nt].x + bi[nt].x;
            v0.y = acc[mt][nt][1] * sc[nt].y + bi[nt].y;
            v1.x = acc[mt][nt][2] * sc[nt].x + bi[nt].x;
            v1.y = acc[mt][nt][3] * sc[nt].y + bi[nt].y;
            *reinterpret_cast<float2*>(o0 + nt * 8) = v0;
            *reinterpret_cast<float2*>(o1 + nt * 8) = v1;
        }
    }
}

// ===================== launch =====================
extern "C" void kernel_launch(void* const* d_in, const int* in_sizes, int n_in,
                              void* d_out, int out_size) {
    const float* inp  = (const float*)d_in[0];   // (4, 2048, 4096) f32
    const int*   wgt  = (const int*)d_in[1];     // (16384, 4096) int32 (int8-valued)
    const float* wsc  = (const float*)d_in[2];   // (16384,) f32
    const float* bias = (const float*)d_in[3];   // (16384,) f32
    float* out = (float*)d_out;                  // (4, 2048, 16384) f32

    (void)in_sizes; (void)n_in; (void)out_size;

    cvtA_kernel<<<16384, 256>>>(reinterpret_cast<const float4*>(inp));
    cvtW_kernel<<<32768, 256>>>(reinterpret_cast<const int4*>(wgt));

    cudaFuncSetAttribute(gemm_f16_hmma,
                         cudaFuncAttributeMaxDynamicSharedMemorySize, SMEM_TOTAL);
    gemm_f16_hmma<<<TILES_M * TILES_N, THREADS, SMEM_TOTAL>>>(out, wsc, bias);
}

// round 5
// speedup vs baseline: 1.1531x; 1.0638x over previous
#include <cuda_runtime.h>
#include <cuda_fp16.h>
#include <cstdint>

// ===================== problem dims =====================
#define M_DIM 8192      // B*S = 4*2048
#define N_DIM 16384
#define K_DIM 4096

#define BM 128
#define BN 128
#define BK 64                         // halves per K-chunk (128 bytes per row)
#define NCHUNK (K_DIM / BK)           // 64
#define STAGES 3
#define THREADS 128                   // 4 warps, 64x64 warp tiles
#define TILES_M (M_DIM / BM)          // 64
#define TILES_N (N_DIM / BN)          // 128
#define GROUP_M 8                     // raster: m-tiles per group (m fastest within group)

// ===================== scratch (alloc-free) =====================
__device__ __half g_A[(size_t)M_DIM * K_DIM];   // 64 MB fp16 activations
__device__ __half g_B[(size_t)N_DIM * K_DIM];   // 128 MB fp16 weights (exact int8 values)

// ===================== PTX helpers (baseline features only) =====================
__device__ __forceinline__ uint32_t smem_to_u32(const void* p) {
    uint32_t a;
    asm("{ .reg .u64 t; cvta.to.shared.u64 t, %1; cvt.u32.u64 %0, t; }" : "=r"(a) : "l"(p));
    return a;
}
__device__ __forceinline__ void cp_async16(uint32_t dst, const void* src) {
    asm volatile("cp.async.cg.shared.global [%0], [%1], 16;" :: "r"(dst), "l"(src));
}
__device__ __forceinline__ void cp_commit() {
    asm volatile("cp.async.commit_group;" ::: "memory");
}
template <int N>
__device__ __forceinline__ void cp_wait() {
    asm volatile("cp.async.wait_group %0;" :: "n"(N) : "memory");
}
__device__ __forceinline__ void ldsm_x4(uint32_t* r, uint32_t addr) {
    asm volatile("ldmatrix.sync.aligned.m8n8.x4.shared.b16 {%0,%1,%2,%3}, [%4];"
                 : "=r"(r[0]), "=r"(r[1]), "=r"(r[2]), "=r"(r[3]) : "r"(addr));
}
__device__ __forceinline__ void mma16816(float* d, const uint32_t* a, const uint32_t* b) {
    asm volatile(
        "mma.sync.aligned.m16n8k16.row.col.f32.f16.f16.f32 "
        "{%0,%1,%2,%3}, {%4,%5,%6,%7}, {%8,%9}, {%0,%1,%2,%3};"
        : "+f"(d[0]), "+f"(d[1]), "+f"(d[2]), "+f"(d[3])
        : "r"(a[0]), "r"(a[1]), "r"(a[2]), "r"(a[3]), "r"(b[0]), "r"(b[1]));
}

// SW128 swizzle for 128B rows: 16B chunk index ^= (row & 7)
__device__ __forceinline__ uint32_t swz_row_col(int row, int colbytes) {
    return (uint32_t)(row * 128) + (uint32_t)(colbytes ^ ((row & 7) << 4));
}

// ===================== SMEM layout =====================
#define A_STAGE_BYTES (BM * 128)              // 16384
#define B_STAGE_BYTES (BN * 128)              // 16384
#define STAGE_BYTES   (A_STAGE_BYTES + B_STAGE_BYTES)   // 32768
#define SMEM_BODY     (STAGES * STAGE_BYTES)  // 98304
#define SMEM_TOTAL    (SMEM_BODY + 128)       // manual 128B alignment headroom

// ===================== conversion kernels =====================
struct alignas(16) H8 { __half2 a, b, c, d; };

__global__ void cvtA_kernel(const float4* __restrict__ in) {
    size_t i = (size_t)blockIdx.x * blockDim.x + threadIdx.x;
    float4 v0 = in[2 * i];
    float4 v1 = in[2 * i + 1];
    H8 h;
    h.a = __floats2half2_rn(v0.x, v0.y);
    h.b = __floats2half2_rn(v0.z, v0.w);
    h.c = __floats2half2_rn(v1.x, v1.y);
    h.d = __floats2half2_rn(v1.z, v1.w);
    reinterpret_cast<H8*>(g_A)[i] = h;
}

__global__ void cvtW_kernel(const int4* __restrict__ in) {
    size_t i = (size_t)blockIdx.x * blockDim.x + threadIdx.x;
    int4 v0 = in[2 * i];
    int4 v1 = in[2 * i + 1];
    H8 h;
    h.a = __floats2half2_rn((float)v0.x, (float)v0.y);
    h.b = __floats2half2_rn((float)v0.z, (float)v0.w);
    h.c = __floats2half2_rn((float)v1.x, (float)v1.y);
    h.d = __floats2half2_rn((float)v1.z, (float)v1.w);
    reinterpret_cast<H8*>(g_B)[i] = h;
}

// ===================== GEMM kernel (HMMA mma.sync, 3-stage cp.async) =====================
// 4 warps, 64x64 warp tiles: 8 LDSM.x4 per 32 MMAs (128 B/MMA vs 192 previously)
__global__ void __launch_bounds__(THREADS, 2)
gemm_f16_hmma(float* __restrict__ out,
              const float* __restrict__ scale,
              const float* __restrict__ bias) {
    extern __shared__ char smem_raw[];
    char* smem = (char*)(((uintptr_t)smem_raw + 127) & ~(uintptr_t)127);
    const uint32_t sb = smem_to_u32(smem);

    const int tid  = threadIdx.x;
    const int wid  = tid >> 5;
    const int lane = tid & 31;
    const int wm   = wid >> 1;   // 0..1  (m-warp, 64 rows)
    const int wn   = wid & 1;    // 0..1  (n-warp, 64 cols)

    // ---- CTA raster swizzle: m fastest within groups of GROUP_M m-tiles ----
    const int bid       = blockIdx.x;
    const int per_group = GROUP_M * TILES_N;           // 1024
    const int g         = bid / per_group;
    const int r_        = bid % per_group;
    const int tile_m    = (g * GROUP_M + (r_ % GROUP_M)) * BM;
    const int tile_n    = (r_ / GROUP_M) * BN;

    const __half* aG = g_A + (size_t)tile_m * K_DIM;
    const __half* bG = g_B + (size_t)tile_n * K_DIM;

    // ldmatrix per-lane row/col-sub mappings (validated round-2 logic)
    const int rowA_in16 = ((lane >> 3) & 1) * 8 + (lane & 7);
    const int ksubA     = ((lane >> 4) & 1) * 16;
    const int rowB_in16 = ((lane >> 4) & 1) * 8 + (lane & 7);
    const int ksubB     = ((lane >> 3) & 1) * 16;

    float acc[4][8][4];
    #pragma unroll
    for (int mt = 0; mt < 4; mt++)
        #pragma unroll
        for (int nt = 0; nt < 8; nt++)
            #pragma unroll
            for (int q = 0; q < 4; q++) acc[mt][nt][q] = 0.0f;

    // ---- producer (all 128 threads): A 128 rows x 8 chunks, B same (16B each) ----
    auto load_stage = [&](int stage, int kc) {
        const uint32_t sA = sb + stage * STAGE_BYTES;
        const uint32_t sB = sA + A_STAGE_BYTES;
        const int kh = kc * BK;   // half offset
        #pragma unroll
        for (int j = 0; j < 8; j++) {
            int idx = tid + j * 128;
            int r = idx >> 3, c = idx & 7;
            cp_async16(sA + swz_row_col(r, c * 16), aG + (size_t)r * K_DIM + kh + c * 8);
        }
        #pragma unroll
        for (int j = 0; j < 8; j++) {
            int idx = tid + j * 128;
            int r = idx >> 3, c = idx & 7;
            cp_async16(sB + swz_row_col(r, c * 16), bG + (size_t)r * K_DIM + kh + c * 8);
        }
    };

    // ---- prologue ----
    #pragma unroll
    for (int s = 0; s < STAGES - 1; s++) {
        load_stage(s, s);
        cp_commit();
    }
    cp_wait<STAGES - 2>();
    __syncthreads();

    // ---- main loop ----
    for (int kc = 0; kc < NCHUNK; kc++) {
        const int kload = kc + STAGES - 1;
        if (kload < NCHUNK) load_stage(kload % STAGES, kload);
        cp_commit();

        const uint32_t sA = sb + (kc % STAGES) * STAGE_BYTES;
        const uint32_t sB = sA + A_STAGE_BYTES;

        #pragma unroll
        for (int ks = 0; ks < 4; ks++) {          // 4 x k16 per BK=64 chunk
            uint32_t a[4][4];
            #pragma unroll
            for (int mt = 0; mt < 4; mt++) {
                const int row = wm * 64 + mt * 16 + rowA_in16;
                ldsm_x4(a[mt], sA + swz_row_col(row, ks * 32 + ksubA));
            }
            uint32_t b[8][2];
            #pragma unroll
            for (int p = 0; p < 4; p++) {         // each x4 covers two n8-tiles
                const int row = wn * 64 + p * 16 + rowB_in16;
                uint32_t r4[4];
                ldsm_x4(r4, sB + swz_row_col(row, ks * 32 + ksubB));
                b[2 * p][0] = r4[0]; b[2 * p][1] = r4[1];
                b[2 * p + 1][0] = r4[2]; b[2 * p + 1][1] = r4[3];
            }
            #pragma unroll
            for (int mt = 0; mt < 4; mt++)
                #pragma unroll
                for (int nt = 0; nt < 8; nt++)
                    mma16816(acc[mt][nt], a[mt], b[nt]);
        }

        cp_wait<STAGES - 2>();
        __syncthreads();
    }

    // ---- epilogue: scale * acc + bias, direct float2 stores ----
    const int colbase = tile_n + wn * 64 + (lane & 3) * 2;
    float2 sc[8], bi[8];
    #pragma unroll
    for (int nt = 0; nt < 8; nt++) {
        sc[nt] = *reinterpret_cast<const float2*>(scale + colbase + nt * 8);
        bi[nt] = *reinterpret_cast<const float2*>(bias  + colbase + nt * 8);
    }

    #pragma unroll
    for (int mt = 0; mt < 4; mt++) {
        const int grow = tile_m + wm * 64 + mt * 16 + (lane >> 2);
        float* o0 = out + (size_t)grow * N_DIM + colbase;
        float* o1 = o0 + (size_t)8 * N_DIM;
        #pragma unroll
        for (int nt = 0; nt < 8; nt++) {
            float2 v0, v1;
            v0.x = acc[mt][nt][0] * sc[nt].x + bi[nt].x;
            v0.y = acc[mt][nt][1] * sc[nt].y + bi[nt].y;
            v1.x = acc[mt][nt][2] * sc[nt].x + bi[nt].x;
            v1.y = acc[mt][nt][3] * sc[nt].y + bi[nt].y;
            *reinterpret_cast<float2*>(o0 + nt * 8) = v0;
            *reinterpret_cast<float2*>(o1 + nt * 8) = v1;
        }
    }
}

// ===================== launch =====================
extern "C" void kernel_launch(void* const* d_in, const int* in_sizes, int n_in,
                              void* d_out, int out_size) {
    const float* inp  = (const float*)d_in[0];   // (4, 2048, 4096) f32
    const int*   wgt  = (const int*)d_in[1];     // (16384, 4096) int32 (int8-valued)
    const float* wsc  = (const float*)d_in[2];   // (16384,) f32
    const float* bias = (const float*)d_in[3];   // (16384,) f32
    float* out = (float*)d_out;                  // (4, 2048, 16384) f32

    (void)in_sizes; (void)n_in; (void)out_size;

    cvtA_kernel<<<16384, 256>>>(reinterpret_cast<const float4*>(inp));
    cvtW_kernel<<<32768, 256>>>(reinterpret_cast<const int4*>(wgt));

    cudaFuncSetAttribute(gemm_f16_hmma,
                         cudaFuncAttributeMaxDynamicSharedMemorySize, SMEM_TOTAL);
    gemm_f16_hmma<<<TILES_M * TILES_N, THREADS, SMEM_TOTAL>>>(out, wsc, bias);
}